// round 12
// baseline (speedup 1.0000x reference)
#include <cuda_runtime.h>
#include <cuda_fp16.h>
#include <cstdint>

#define BB 32
#define LL 2048
#define DD 64
#define NKT 16            // 2048 / 128
#define SCSTR 2056        // score row stride in HALFS (4112 B, +8 pad)

// fused-kernel smem byte offsets
#define SC_OFF   0                    // half[32][SCSTR]   = 131584
#define QS_OFF   131584               // half[32][72]      = 4608
#define KS_OFF   136192               // 2 x half[128][72] = 2 x 18432
#define VS_OFF   173056               // 2 x 18432
#define RED_OFF  136192               // O-reduce area (reuses KS/VS, 64 KB)
#define PART_OFF 209920               // float[32*8]
#define RINV_OFF 210944               // float[32]
#define SMEM_TOTAL 211072

__device__ __half g_qh[(size_t)BB * LL * DD];
__device__ __half g_kh[(size_t)BB * LL * DD];
__device__ __half g_vh[(size_t)BB * LL * DD];

// ---------------- helpers ----------------
__device__ __forceinline__ uint32_t smem_u32(const void* p) {
    uint32_t a;
    asm("{ .reg .u64 t; cvta.to.shared.u64 t, %1; cvt.u32.u64 %0, t; }" : "=r"(a) : "l"(p));
    return a;
}
__device__ __forceinline__ void ldsm_x4(uint32_t addr, uint32_t* r) {
    asm volatile("ldmatrix.sync.aligned.m8n8.x4.shared.b16 {%0,%1,%2,%3}, [%4];"
                 : "=r"(r[0]), "=r"(r[1]), "=r"(r[2]), "=r"(r[3]) : "r"(addr));
}
__device__ __forceinline__ void ldsm_x4t(uint32_t addr, uint32_t* r) {
    asm volatile("ldmatrix.sync.aligned.m8n8.x4.trans.shared.b16 {%0,%1,%2,%3}, [%4];"
                 : "=r"(r[0]), "=r"(r[1]), "=r"(r[2]), "=r"(r[3]) : "r"(addr));
}
__device__ __forceinline__ void mma_f16(float* c, const uint32_t* a, const uint32_t* b) {
    asm volatile(
        "mma.sync.aligned.m16n8k16.row.col.f32.f16.f16.f32 "
        "{%0,%1,%2,%3}, {%4,%5,%6,%7}, {%8,%9}, {%0,%1,%2,%3};"
        : "+f"(c[0]), "+f"(c[1]), "+f"(c[2]), "+f"(c[3])
        : "r"(a[0]), "r"(a[1]), "r"(a[2]), "r"(a[3]), "r"(b[0]), "r"(b[1]));
}
__device__ __forceinline__ void cp16(uint32_t saddr, const void* g) {
    asm volatile("cp.async.cg.shared.global [%0], [%1], 16;" :: "r"(saddr), "l"(g));
}
__device__ __forceinline__ uint32_t h2pack(float a, float b) {
    __half2 h = __floats2half2_rn(a, b);
    return *(uint32_t*)&h;
}

// ---------- Kernel 1: normalize q,k -> fp16; convert v -> fp16 ----------
__global__ __launch_bounds__(256) void norm_kernel(const float* __restrict__ q,
                                                   const float* __restrict__ k,
                                                   const float* __restrict__ v) {
    int t = threadIdx.x;
    int rowInBlk = t >> 4;
    int lane = t & 15;
    long long row = (long long)blockIdx.x * 16 + rowInBlk;
    const long long BL = (long long)BB * LL;

    const float* src;
    __half* dst;
    bool donorm = true;
    long long r2 = row;
    if (r2 < BL) { src = q; dst = g_qh; }
    else if (r2 < 2 * BL) { src = k; dst = g_kh; r2 -= BL; }
    else { src = v; dst = g_vh; r2 -= 2 * BL; donorm = false; }

    const float4 w = *(const float4*)(src + r2 * DD + lane * 4);
    float ss = w.x * w.x + w.y * w.y + w.z * w.z + w.w * w.w;
#pragma unroll
    for (int o = 8; o; o >>= 1) ss += __shfl_xor_sync(0xffffffffu, ss, o, 16);
    float inv = donorm ? (1.0f / fmaxf(sqrtf(ss), 1e-12f)) : 1.0f;
    uint2 u;
    u.x = h2pack(w.x * inv, w.y * inv);
    u.y = h2pack(w.z * inv, w.w * inv);
    *(uint2*)(dst + r2 * DD + lane * 4) = u;
}

// ---------- Fused kernel: QK once -> rowsums + scores(smem) + PV ----------
// grid (LL/32 = 64, BB), 256 thr (8 warps). Warp w owns k-cols w*16 of each tile.
__global__ __launch_bounds__(256, 1) void fused_kernel(const int* __restrict__ mask,
                                                       float* __restrict__ attn,
                                                       float* __restrict__ out) {
    extern __shared__ char smem[];
    __half* sc   = (__half*)(smem + SC_OFF);
    __half* q_s  = (__half*)(smem + QS_OFF);
    float*  part = (float*)(smem + PART_OFF);
    float*  rinv = (float*)(smem + RINV_OFF);
    const uint32_t smb = smem_u32(smem);

    const int b  = blockIdx.y;
    const int q0 = blockIdx.x * 32;
    const int t  = threadIdx.x;
    const int w  = t >> 5, lane = t & 31;
    const int g  = lane >> 2, c = lane & 3;

    const __half* kbase = g_kh + (size_t)b * LL * DD;
    const __half* vbase = g_vh + (size_t)b * LL * DD;

    // stage q tile [32][64]
    {
        int r = t >> 3, col = (t & 7) * 8;
        *(uint4*)&q_s[r * 72 + col] =
            *(const uint4*)(g_qh + ((size_t)b * LL + q0 + r) * DD + col);
    }
    // prologue: cp.async stage tile 0 into buffer 0
#pragma unroll
    for (int i = 0; i < 4; i++) {
        int idx = t + i * 256;
        int r = idx >> 3, seg = idx & 7;
        cp16(smb + KS_OFF + r * 144 + seg * 16, kbase + (size_t)r * 64 + seg * 8);
        cp16(smb + VS_OFF + r * 144 + seg * 16, vbase + (size_t)r * 64 + seg * 8);
    }
    asm volatile("cp.async.commit_group;");
    __syncthreads();   // q_s visible

    // q fragments (load once): aq[mf][s][4]
    uint32_t aq[2][4][4];
    {
        const uint32_t aptr = smb + QS_OFF + (uint32_t)(lane & 15) * 144 + (lane >> 4) * 16;
#pragma unroll
        for (int mf = 0; mf < 2; mf++)
#pragma unroll
            for (int s = 0; s < 4; s++)
                ldsm_x4(aptr + (uint32_t)mf * 2304 + s * 32, aq[mf][s]);
    }

    const uint32_t bpbase = smb + KS_OFF +
        (uint32_t)(w * 16 + ((lane >> 4) << 3) + (lane & 7)) * 144 + ((lane >> 3) & 1) * 16;
    const uint32_t vpbase = smb + VS_OFF +
        (uint32_t)(w * 16 + (lane & 15)) * 144 + (lane >> 4) * 16;

    const int* mbase0 = mask + ((size_t)b * LL + q0 + g) * LL + w * 16 + c * 4;

    float oacc[2][8][4];
#pragma unroll
    for (int mf = 0; mf < 2; mf++)
#pragma unroll
        for (int nf = 0; nf < 8; nf++)
#pragma unroll
            for (int e = 0; e < 4; e++) oacc[mf][nf][e] = 0.f;

    float rs[4] = {0.f, 0.f, 0.f, 0.f};

    for (int kt = 0; kt < NKT; kt++) {
        const int buf = kt & 1;
        asm volatile("cp.async.wait_group 0;");
        __syncthreads();   // current buffers ready; prev compute done with next buf

        // prefetch mask (int4, latency hidden behind MMAs)
        int4 mm[4];
#pragma unroll
        for (int i = 0; i < 4; i++)
            mm[i] = __ldcs((const int4*)(mbase0 + (size_t)(8 * i) * LL + kt * 128));

        // stage next tile into other buffer
        if (kt + 1 < NKT) {
            const int nb = (kt + 1) & 1;
            const __half* kn = kbase + (size_t)(kt + 1) * 128 * 64;
            const __half* vn = vbase + (size_t)(kt + 1) * 128 * 64;
#pragma unroll
            for (int i = 0; i < 4; i++) {
                int idx = t + i * 256;
                int r = idx >> 3, seg = idx & 7;
                cp16(smb + KS_OFF + nb * 18432 + r * 144 + seg * 16, kn + (size_t)r * 64 + seg * 8);
                cp16(smb + VS_OFF + nb * 18432 + r * 144 + seg * 16, vn + (size_t)r * 64 + seg * 8);
            }
        }
        asm volatile("cp.async.commit_group;");

        // QK: M32 x N16 x K64
        float acc[2][2][4];
#pragma unroll
        for (int mf = 0; mf < 2; mf++)
#pragma unroll
            for (int nf = 0; nf < 2; nf++)
#pragma unroll
                for (int e = 0; e < 4; e++) acc[mf][nf][e] = 0.f;

        const uint32_t bp = bpbase + (uint32_t)buf * 18432;
#pragma unroll
        for (int s = 0; s < 4; s++) {
            uint32_t bb[4];
            ldsm_x4(bp + s * 32, bb);
            mma_f16(acc[0][0], aq[0][s], bb);
            mma_f16(acc[0][1], aq[0][s], bb + 2);
            mma_f16(acc[1][0], aq[1][s], bb);
            mma_f16(acc[1][1], aq[1][s], bb + 2);
        }

        // pack mask bits: lane ends with 16-bit masks for rows g, g+8, g+16, g+24
        uint32_t mr[4];
#pragma unroll
        for (int i = 0; i < 4; i++) {
            int4 m = mm[i];
            uint32_t nib = (uint32_t)(m.x != 0) | ((uint32_t)(m.y != 0) << 1) |
                           ((uint32_t)(m.z != 0) << 2) | ((uint32_t)(m.w != 0) << 3);
            uint32_t v = nib << (c * 4);
            v |= __shfl_xor_sync(0xffffffffu, v, 1);
            v |= __shfl_xor_sync(0xffffffffu, v, 2);
            mr[i] = v;
        }

        // epilogue: masked s+1 -> rowsums, fp16 scores, PV A-frags
        uint32_t af[2][4];
#pragma unroll
        for (int mf = 0; mf < 2; mf++) {
            uint32_t mA = mr[mf * 2], mB = mr[mf * 2 + 1];
#pragma unroll
            for (int nf = 0; nf < 2; nf++) {
                int bidx = nf * 8 + 2 * c;
                float s0 = ((mA >> bidx) & 1u)       ? 0.f : acc[mf][nf][0] + 1.f;
                float s1 = ((mA >> (bidx + 1)) & 1u) ? 0.f : acc[mf][nf][1] + 1.f;
                float s2 = ((mB >> bidx) & 1u)       ? 0.f : acc[mf][nf][2] + 1.f;
                float s3 = ((mB >> (bidx + 1)) & 1u) ? 0.f : acc[mf][nf][3] + 1.f;
                rs[mf * 2 + 0] += s0 + s1;
                rs[mf * 2 + 1] += s2 + s3;
                uint32_t hA = h2pack(s0, s1);
                uint32_t hB = h2pack(s2, s3);
                af[mf][nf * 2]     = hA;
                af[mf][nf * 2 + 1] = hB;
                int col = kt * 128 + w * 16 + nf * 8 + 2 * c;
                *(uint32_t*)&sc[(mf * 16 + g) * SCSTR + col]     = hA;
                *(uint32_t*)&sc[(mf * 16 + g + 8) * SCSTR + col] = hB;
            }
        }

        // PV partial: M32 x N64 x K16 (A from registers)
        const uint32_t vp = vpbase + (uint32_t)buf * 18432;
#pragma unroll
        for (int db = 0; db < 4; db++) {
            uint32_t bb[4];
            ldsm_x4t(vp + db * 32, bb);
            mma_f16(oacc[0][db * 2],     af[0], bb);
            mma_f16(oacc[0][db * 2 + 1], af[0], bb + 2);
            mma_f16(oacc[1][db * 2],     af[1], bb);
            mma_f16(oacc[1][db * 2 + 1], af[1], bb + 2);
        }
    }

    // rowsums -> rinv
#pragma unroll
    for (int i = 0; i < 4; i++) {
        float vs = rs[i];
        vs += __shfl_xor_sync(0xffffffffu, vs, 1);
        vs += __shfl_xor_sync(0xffffffffu, vs, 2);
        if (c == 0) {
            int r = (i >> 1) * 16 + (i & 1) * 8 + g;
            part[r * 8 + w] = vs;
        }
    }
    __syncthreads();
    if (t < 32) {
        float s = 0.f;
#pragma unroll
        for (int j = 0; j < 8; j++) s += part[t * 8 + j];
        rinv[t] = 1.0f / fmaxf(s, 1e-12f);
    }
    __syncthreads();

    // O cross-warp reduce via smem (reuses k/v buffers — cp.async all drained)
    {
        float* red = (float*)(smem + RED_OFF) + (size_t)w * 2048;
#pragma unroll
        for (int mf = 0; mf < 2; mf++)
#pragma unroll
            for (int nf = 0; nf < 8; nf++)
#pragma unroll
                for (int e = 0; e < 4; e++)
                    red[((mf * 8 + nf) * 4 + e) * 32 + lane] = oacc[mf][nf][e];
    }
    __syncthreads();
    {
        const float* red = (const float*)(smem + RED_OFF);
        int r = t >> 3, d0 = (t & 7) * 8;
        float ri = rinv[r];
        int mf = r >> 4, gg = r & 7, ehi = (r >> 3) & 1;
        float ov[8];
#pragma unroll
        for (int j = 0; j < 8; j++) {
            int d = d0 + j;
            int nf = d >> 3, cc = (d & 7) >> 1, elo = d & 1;
            int idx = ((mf * 8 + nf) * 4 + ehi * 2 + elo) * 32 + gg * 4 + cc;
            float s = 0.f;
#pragma unroll
            for (int ww = 0; ww < 8; ww++) s += red[(size_t)ww * 2048 + idx];
            ov[j] = s * ri;
        }
        float* op = out + ((size_t)b * LL + q0 + r) * DD + d0;
        *(float4*)op       = make_float4(ov[0], ov[1], ov[2], ov[3]);
        *(float4*)(op + 4) = make_float4(ov[4], ov[5], ov[6], ov[7]);
    }

    // final attn write (normalized fp32), fully coalesced
#pragma unroll 4
    for (int r = 0; r < 32; r++) {
        float ri = rinv[r];
        float* arow = attn + ((size_t)b * LL + q0 + r) * LL;
#pragma unroll
        for (int h = 0; h < 2; h++) {
            int col = h * 1024 + 4 * t;
            const __half2* p = (const __half2*)&sc[r * SCSTR + col];
            __half2 h0 = p[0], h1 = p[1];
            float2 f0 = __half22float2(h0);
            float2 f1 = __half22float2(h1);
            __stcs((float4*)(arow + col),
                   make_float4(f0.x * ri, f0.y * ri, f1.x * ri, f1.y * ri));
        }
    }
}

// ---------------- launch ----------------
extern "C" void kernel_launch(void* const* d_in, const int* in_sizes, int n_in,
                              void* d_out, int out_size) {
    const float* q = (const float*)d_in[0];
    const float* k = (const float*)d_in[1];
    const float* v = (const float*)d_in[2];
    const int* mask = (const int*)d_in[3];

    float* out = (float*)d_out;
    float* attn = out + (size_t)BB * LL * DD;

    cudaFuncSetAttribute(fused_kernel, cudaFuncAttributeMaxDynamicSharedMemorySize,
                         SMEM_TOTAL);

    norm_kernel<<<(3 * BB * LL) / 16, 256>>>(q, k, v);
    fused_kernel<<<dim3(LL / 32, BB), 256, SMEM_TOTAL>>>(mask, attn, out);
}

// round 13
// speedup vs baseline: 1.2561x; 1.2561x over previous
#include <cuda_runtime.h>
#include <cuda_fp16.h>
#include <cstdint>

#define BB 32
#define LL 2048
#define DD 64
#define NKT 16            // 2048 / 128
#define SSP 136           // s_s row stride (halfs)

// merged-kernel smem byte offsets (total 93696 -> 2 CTAs/SM)
#define QS_OFF   0          // half[128][72] = 18432
#define KS_OFF   18432      // half[128][72] = 18432 (phase1 k buf0, phase2 k)
#define VS_OFF   36864      // half[128][72] = 18432 (phase1 k buf1, phase2 v)
#define SS_OFF   55296      // half[128][136] = 34816
#define BMT_OFF  90112      // uint32[512] = 2048
#define PART_OFF 92160      // float[256] = 1024
#define RINV_OFF 93184      // float[128] = 512
#define SMEM_TOTAL 93696

__device__ __half   g_qh[(size_t)BB * LL * DD];
__device__ __half   g_kh[(size_t)BB * LL * DD];
__device__ __half   g_vh[(size_t)BB * LL * DD];
__device__ uint32_t g_bm[(size_t)BB * LL * (LL / 32)];   // 16.8 MB bitmask

// ---------------- helpers ----------------
__device__ __forceinline__ uint32_t smem_u32(const void* p) {
    uint32_t a;
    asm("{ .reg .u64 t; cvta.to.shared.u64 t, %1; cvt.u32.u64 %0, t; }" : "=r"(a) : "l"(p));
    return a;
}
__device__ __forceinline__ void ldsm_x4(uint32_t addr, uint32_t* r) {
    asm volatile("ldmatrix.sync.aligned.m8n8.x4.shared.b16 {%0,%1,%2,%3}, [%4];"
                 : "=r"(r[0]), "=r"(r[1]), "=r"(r[2]), "=r"(r[3]) : "r"(addr));
}
__device__ __forceinline__ void ldsm_x4t(uint32_t addr, uint32_t* r) {
    asm volatile("ldmatrix.sync.aligned.m8n8.x4.trans.shared.b16 {%0,%1,%2,%3}, [%4];"
                 : "=r"(r[0]), "=r"(r[1]), "=r"(r[2]), "=r"(r[3]) : "r"(addr));
}
__device__ __forceinline__ void mma_f16(float* c, const uint32_t* a, const uint32_t* b) {
    asm volatile(
        "mma.sync.aligned.m16n8k16.row.col.f32.f16.f16.f32 "
        "{%0,%1,%2,%3}, {%4,%5,%6,%7}, {%8,%9}, {%0,%1,%2,%3};"
        : "+f"(c[0]), "+f"(c[1]), "+f"(c[2]), "+f"(c[3])
        : "r"(a[0]), "r"(a[1]), "r"(a[2]), "r"(a[3]), "r"(b[0]), "r"(b[1]));
}
__device__ __forceinline__ void cp16(uint32_t saddr, const void* g) {
    asm volatile("cp.async.cg.shared.global [%0], [%1], 16;" :: "r"(saddr), "l"(g));
}
__device__ __forceinline__ uint32_t h2pack(float a, float b) {
    __half2 h = __floats2half2_rn(a, b);
    return *(uint32_t*)&h;
}

// ---------- Kernel 1: normalize q,k -> fp16; convert v -> fp16 ----------
__global__ __launch_bounds__(256) void norm_kernel(const float* __restrict__ q,
                                                   const float* __restrict__ k,
                                                   const float* __restrict__ v) {
    int t = threadIdx.x;
    int rowInBlk = t >> 4;
    int lane = t & 15;
    long long row = (long long)blockIdx.x * 16 + rowInBlk;
    const long long BL = (long long)BB * LL;

    const float* src;
    __half* dst;
    bool donorm = true;
    long long r2 = row;
    if (r2 < BL) { src = q; dst = g_qh; }
    else if (r2 < 2 * BL) { src = k; dst = g_kh; r2 -= BL; }
    else { src = v; dst = g_vh; r2 -= 2 * BL; donorm = false; }

    const float4 w = *(const float4*)(src + r2 * DD + lane * 4);
    float ss = w.x * w.x + w.y * w.y + w.z * w.z + w.w * w.w;
#pragma unroll
    for (int o = 8; o; o >>= 1) ss += __shfl_xor_sync(0xffffffffu, ss, o, 16);
    float inv = donorm ? (1.0f / fmaxf(sqrtf(ss), 1e-12f)) : 1.0f;
    uint2 u;
    u.x = h2pack(w.x * inv, w.y * inv);
    u.y = h2pack(w.z * inv, w.w * inv);
    *(uint2*)(dst + r2 * DD + lane * 4) = u;
}

// ---------- Merged kernel: phase1 rowsums+bitmask, phase2 attn+PV ----------
// grid (16, 32), 256 thr (8 warps), 2 CTAs/SM.
__global__ __launch_bounds__(256, 2) void merged_kernel(const int* __restrict__ mask,
                                                        float* __restrict__ attn,
                                                        float* __restrict__ out) {
    extern __shared__ char smem[];
    __half*   s_s  = (__half*)(smem + SS_OFF);
    uint32_t* bmt  = (uint32_t*)(smem + BMT_OFF);
    float*    part = (float*)(smem + PART_OFF);
    float*    rinv = (float*)(smem + RINV_OFF);
    const uint32_t smb = smem_u32(smem);

    const int b  = blockIdx.y;
    const int q0 = blockIdx.x * 128;
    const int t  = threadIdx.x;
    const int w  = t >> 5, lane = t & 31;
    const int g  = lane >> 2, c = lane & 3;

    const __half* kn = g_kh + (size_t)b * LL * DD;
    const __half* vn = g_vh + (size_t)b * LL * DD;

    // stage q tile [128][64]
    {
        int r = t >> 1, sg = (t & 1) * 32;
        const __half* qp = g_qh + ((size_t)b * LL + q0 + r) * DD + sg;
#pragma unroll
        for (int i = 0; i < 4; i++)
            *(uint4*)((__half*)(smem + QS_OFF) + r * 72 + sg + i * 8) =
                *(const uint4*)(qp + i * 8);
    }
    // prologue: cp.async k tile 0 -> buf0 (KS)
#pragma unroll
    for (int i = 0; i < 4; i++) {
        int idx = t + i * 256;
        int r = idx >> 3, seg = idx & 7;
        cp16(smb + KS_OFF + r * 144 + seg * 16, kn + (size_t)r * 64 + seg * 8);
    }
    asm volatile("cp.async.commit_group;");
    __syncthreads();   // q_s visible

    // ================= Phase 1: rowsums + bitmask =================
    {
        const int m0 = (w & 3) * 32, ni = w >> 2, n0 = ni * 64;
        const uint32_t aptr = smb + QS_OFF + (uint32_t)(m0 + (lane & 15)) * 144 + (lane >> 4) * 16;
        const uint32_t bptr = smb + KS_OFF +
            (uint32_t)(n0 + ((lane >> 4) << 3) + (lane & 7)) * 144 + ((lane >> 3) & 1) * 16;

        float rs[4] = {0.f, 0.f, 0.f, 0.f};

        for (int kt = 0; kt < NKT; kt++) {
            const int buf = kt & 1;
            __syncthreads();   // prev epilogue done with bmt; prev MMA done with prefetch buf
            // prefetch next k tile into other buffer (VS area = buf1)
            if (kt + 1 < NKT) {
                const int nb = (kt + 1) & 1;
                const __half* kp = kn + (size_t)(kt + 1) * 128 * 64;
#pragma unroll
                for (int i = 0; i < 4; i++) {
                    int idx = t + i * 256;
                    int r = idx >> 3, seg = idx & 7;
                    cp16(smb + KS_OFF + nb * 18432 + r * 144 + seg * 16,
                         kp + (size_t)r * 64 + seg * 8);
                }
            }
            asm volatile("cp.async.commit_group;");

            // ballot bitpack: warp w handles rows w*16..w*16+15
            {
                const int* mbase = mask + ((size_t)b * LL + q0) * LL + (size_t)kt * 128;
#pragma unroll
                for (int i = 0; i < 16; i++) {
                    int row = w * 16 + i;
                    const int* mr = mbase + (size_t)row * LL;
#pragma unroll
                    for (int wq = 0; wq < 4; wq++) {
                        int mv = __ldcs(mr + wq * 32 + lane);
                        uint32_t bits = __ballot_sync(0xffffffffu, mv != 0);
                        if (lane == wq) bmt[row * 4 + wq] = bits;
                    }
                }
            }
            asm volatile("cp.async.wait_group 1;");
            __syncthreads();   // bmt + k_s(kt) visible

            // persist bitmask tile (same CTA reads it back in phase 2; L2-hot)
            if (t < 128)
                *(uint4*)&g_bm[((size_t)b * LL + q0 + t) * 64 + kt * 4] =
                    *(const uint4*)&bmt[t * 4];

            // QK MMA: warp = M32 x N64
            float acc[2][8][4];
#pragma unroll
            for (int mf = 0; mf < 2; mf++)
#pragma unroll
                for (int nf = 0; nf < 8; nf++)
#pragma unroll
                    for (int e = 0; e < 4; e++) acc[mf][nf][e] = 0.f;

            const uint32_t bp = bptr + (uint32_t)buf * 18432;
#pragma unroll
            for (int s = 0; s < 4; s++) {
                uint32_t a0[4], a1[4];
                ldsm_x4(aptr + s * 32, a0);
                ldsm_x4(aptr + 16 * 144 + s * 32, a1);
#pragma unroll
                for (int nfp = 0; nfp < 4; nfp++) {
                    uint32_t bb[4];
                    ldsm_x4(bp + (uint32_t)nfp * 16 * 144 + s * 32, bb);
                    mma_f16(acc[0][nfp * 2],     a0, bb);
                    mma_f16(acc[0][nfp * 2 + 1], a0, bb + 2);
                    mma_f16(acc[1][nfp * 2],     a1, bb);
                    mma_f16(acc[1][nfp * 2 + 1], a1, bb + 2);
                }
            }

            // rowsum epilogue (bits from smem)
#pragma unroll
            for (int mf = 0; mf < 2; mf++) {
                int r0 = m0 + mf * 16 + g;
#pragma unroll
                for (int nf = 0; nf < 8; nf++) {
                    int col = n0 + nf * 8 + 2 * c;
                    uint32_t wA = bmt[r0 * 4 + (col >> 5)];
                    uint32_t wB = bmt[(r0 + 8) * 4 + (col >> 5)];
                    int sh = col & 31;
                    float s0 = ((wA >> sh) & 1u)       ? 0.f : acc[mf][nf][0] + 1.f;
                    float s1 = ((wA >> (sh + 1)) & 1u) ? 0.f : acc[mf][nf][1] + 1.f;
                    float s2 = ((wB >> sh) & 1u)       ? 0.f : acc[mf][nf][2] + 1.f;
                    float s3 = ((wB >> (sh + 1)) & 1u) ? 0.f : acc[mf][nf][3] + 1.f;
                    rs[mf * 2 + 0] += s0 + s1;
                    rs[mf * 2 + 1] += s2 + s3;
                }
            }
        }

        // rowsums: reduce over c lanes, combine two ni halves via smem
#pragma unroll
        for (int i = 0; i < 4; i++) {
            float vs = rs[i];
            vs += __shfl_xor_sync(0xffffffffu, vs, 1);
            vs += __shfl_xor_sync(0xffffffffu, vs, 2);
            rs[i] = vs;
        }
        if (c == 0) {
            part[(m0 + g) * 2 + ni]      = rs[0];
            part[(m0 + g + 8) * 2 + ni]  = rs[1];
            part[(m0 + 16 + g) * 2 + ni] = rs[2];
            part[(m0 + 24 + g) * 2 + ni] = rs[3];
        }
        __syncthreads();
        if (t < 128) rinv[t] = 1.0f / fmaxf(part[t * 2] + part[t * 2 + 1], 1e-12f);
        __syncthreads();
    }

    // ================= Phase 2: QK recompute -> attn write + PV =================
    {
        const int r0 = w * 16;
        const uint32_t aptr = smb + QS_OFF + (uint32_t)(r0 + (lane & 15)) * 144 + (lane >> 4) * 16;
        const uint32_t bptr = smb + KS_OFF +
            (uint32_t)(((lane >> 4) << 3) + (lane & 7)) * 144 + ((lane >> 3) & 1) * 16;
        const uint32_t vptr = smb + VS_OFF + (uint32_t)(lane & 15) * 144 + (lane >> 4) * 16;

        float oacc[8][4];
#pragma unroll
        for (int nb = 0; nb < 8; nb++)
#pragma unroll
            for (int e = 0; e < 4; e++) oacc[nb][e] = 0.f;

        const uint32_t* bmrA = g_bm + ((size_t)b * LL + q0 + r0 + g) * 64;
        const uint32_t* bmrB = bmrA + (size_t)8 * 64;

        for (int kt = 0; kt < NKT; kt++) {
            __syncthreads();   // all warps done with k_s/v_s of prev tile
            {
                const __half* kp = kn + (size_t)kt * 128 * 64;
                const __half* vp = vn + (size_t)kt * 128 * 64;
#pragma unroll
                for (int i = 0; i < 4; i++) {
                    int idx = t + i * 256;
                    int r = idx >> 3, seg = idx & 7;
                    cp16(smb + KS_OFF + r * 144 + seg * 16, kp + (size_t)r * 64 + seg * 8);
                    cp16(smb + VS_OFF + r * 144 + seg * 16, vp + (size_t)r * 64 + seg * 8);
                }
            }
            asm volatile("cp.async.commit_group;");
            // bitmask for this thread's two rows (written by this CTA, L2-hot)
            uint4 bA = *(const uint4*)(bmrA + kt * 4);
            uint4 bB = *(const uint4*)(bmrB + kt * 4);
            uint32_t bmA[4] = {bA.x, bA.y, bA.z, bA.w};
            uint32_t bmB[4] = {bB.x, bB.y, bB.z, bB.w};
            asm volatile("cp.async.wait_group 0;");
            __syncthreads();

            // two 64-col halves: QK -> epilogue -> PV (A from registers)
#pragma unroll
            for (int h = 0; h < 2; h++) {
                float acc[8][4];
#pragma unroll
                for (int nf = 0; nf < 8; nf++)
#pragma unroll
                    for (int e = 0; e < 4; e++) acc[nf][e] = 0.f;

#pragma unroll
                for (int s = 0; s < 4; s++) {
                    uint32_t a[4];
                    ldsm_x4(aptr + s * 32, a);
#pragma unroll
                    for (int nb = 0; nb < 4; nb++) {
                        uint32_t bb[4];
                        ldsm_x4(bptr + (uint32_t)(h * 4 + nb) * 2304 + s * 32, bb);
                        mma_f16(acc[nb * 2],     a, bb);
                        mma_f16(acc[nb * 2 + 1], a, bb + 2);
                    }
                }

#pragma unroll
                for (int ks = 0; ks < 4; ks++) {
                    uint32_t af[4];
#pragma unroll
                    for (int p = 0; p < 2; p++) {
                        int nf = 2 * ks + p;
                        int col = h * 64 + nf * 8 + 2 * c;
                        uint32_t wA = bmA[col >> 5];
                        uint32_t wB = bmB[col >> 5];
                        int sh = col & 31;
                        float s0 = ((wA >> sh) & 1u)       ? 0.f : acc[nf][0] + 1.f;
                        float s1 = ((wA >> (sh + 1)) & 1u) ? 0.f : acc[nf][1] + 1.f;
                        float s2 = ((wB >> sh) & 1u)       ? 0.f : acc[nf][2] + 1.f;
                        float s3 = ((wB >> (sh + 1)) & 1u) ? 0.f : acc[nf][3] + 1.f;
                        uint32_t hA = h2pack(s0, s1);
                        uint32_t hB = h2pack(s2, s3);
                        af[p * 2]     = hA;
                        af[p * 2 + 1] = hB;
                        *(uint32_t*)&s_s[(r0 + g) * SSP + col]     = hA;
                        *(uint32_t*)&s_s[(r0 + g + 8) * SSP + col] = hB;
                    }
                    int gks = h * 4 + ks;
#pragma unroll
                    for (int db = 0; db < 4; db++) {
                        uint32_t bb[4];
                        ldsm_x4t(vptr + (uint32_t)gks * 2304 + db * 32, bb);
                        mma_f16(oacc[db * 2],     af, bb);
                        mma_f16(oacc[db * 2 + 1], af, bb + 2);
                    }
                }
            }

            __syncwarp();   // s_s rows complete within warp
            // attn write (normalized fp32), warp-private rows, coalesced
#pragma unroll
            for (int i = 0; i < 16; i++) {
                int row = r0 + i;
                uint2 raw = *(const uint2*)&s_s[row * SSP + lane * 4];
                float ri = rinv[row];
                float2 f0 = __half22float2(*(__half2*)&raw.x);
                float2 f1 = __half22float2(*(__half2*)&raw.y);
                float4 o = make_float4(f0.x * ri, f0.y * ri, f1.x * ri, f1.y * ri);
                __stcs((float4*)(attn + ((size_t)b * LL + q0 + row) * LL +
                                 (size_t)kt * 128 + lane * 4), o);
            }
            __syncwarp();
        }

        // O epilogue: scale rows by rinv, write
        float riA = rinv[r0 + g], riB = rinv[r0 + g + 8];
        float* o0 = out + ((size_t)b * LL + q0 + r0 + g) * DD;
        float* o1 = o0 + (size_t)8 * DD;
#pragma unroll
        for (int nb = 0; nb < 8; nb++) {
            int col = nb * 8 + 2 * c;
            *(float2*)(o0 + col) = make_float2(oacc[nb][0] * riA, oacc[nb][1] * riA);
            *(float2*)(o1 + col) = make_float2(oacc[nb][2] * riB, oacc[nb][3] * riB);
        }
    }
}

// ---------------- launch ----------------
extern "C" void kernel_launch(void* const* d_in, const int* in_sizes, int n_in,
                              void* d_out, int out_size) {
    const float* q = (const float*)d_in[0];
    const float* k = (const float*)d_in[1];
    const float* v = (const float*)d_in[2];
    const int* mask = (const int*)d_in[3];

    float* out = (float*)d_out;
    float* attn = out + (size_t)BB * LL * DD;

    cudaFuncSetAttribute(merged_kernel, cudaFuncAttributeMaxDynamicSharedMemorySize,
                         SMEM_TOTAL);

    norm_kernel<<<(3 * BB * LL) / 16, 256>>>(q, k, v);
    merged_kernel<<<dim3(LL / 128, BB), 256, SMEM_TOTAL>>>(mask, attn, out);
}